// round 1
// baseline (speedup 1.0000x reference)
#include <cuda_runtime.h>
#include <cstdint>

// out[b,h,i,j] = mask[b,h,i,j] - |slope[h] * (i - j)|
// B=2, NH=16, L=2048  -> 134,217,728 fp32 elems = 33,554,432 float4
// slope[h] = 2^(-0.5*(h+1))  for NH=16 (power of two -> closed form)

static constexpr int L_LOG2   = 11;          // L = 2048
static constexpr int NH_MASK  = 15;          // NH = 16
static constexpr long long N_ELEM = 2LL * 16 * 2048 * 2048;
static constexpr long long N_VEC  = N_ELEM / 4;

__global__ __launch_bounds__(256)
void alibi_kernel(const float4* __restrict__ mask, float4* __restrict__ out) {
    long long v = (long long)blockIdx.x * blockDim.x + threadIdx.x;
    if (v >= N_VEC) return;

    long long idx = v << 2;                         // scalar element index
    int j = (int)(idx & ((1 << L_LOG2) - 1));       // 0..2047, consecutive 4
    int i = (int)((idx >> L_LOG2) & ((1 << L_LOG2) - 1));
    int h = (int)((idx >> (2 * L_LOG2)) & NH_MASK);

    float slope = exp2f(-0.5f * (float)(h + 1));

    float4 m = mask[v];
    float base = (float)(i - j);                    // rel for j; j+1 => base-1 ...
    float4 r;
    r.x = m.x - fabsf(slope * (base - 0.0f));
    r.y = m.y - fabsf(slope * (base - 1.0f));
    r.z = m.z - fabsf(slope * (base - 2.0f));
    r.w = m.w - fabsf(slope * (base - 3.0f));
    out[v] = r;
}

extern "C" void kernel_launch(void* const* d_in, const int* in_sizes, int n_in,
                              void* d_out, int out_size) {
    // inputs: mask (B,NH,L,L) f32, q, k, v  — only mask is needed
    const float4* mask = (const float4*)d_in[0];
    float4* out = (float4*)d_out;

    const int threads = 256;
    const long long blocks = (N_VEC + threads - 1) / threads;   // 131072
    alibi_kernel<<<(unsigned)blocks, threads>>>(mask, out);
}

// round 2
// speedup vs baseline: 1.0004x; 1.0004x over previous
#include <cuda_runtime.h>
#include <cstdint>

// out[b,h,i,j] = mask[b,h,i,j] - |slope[h] * (i - j)|
// B=2, NH=16, L=2048  -> 134,217,728 fp32 elems = 33,554,432 float4
// slope[h] = 2^(-0.5*(h+1))  for NH=16 (power of two -> closed form)

static constexpr int L_LOG2   = 11;          // L = 2048
static constexpr int NH_MASK  = 15;          // NH = 16
static constexpr long long N_ELEM = 2LL * 16 * 2048 * 2048;
static constexpr long long N_VEC  = N_ELEM / 4;

__global__ __launch_bounds__(256)
void alibi_kernel(const float4* __restrict__ mask, float4* __restrict__ out) {
    long long v = (long long)blockIdx.x * blockDim.x + threadIdx.x;
    if (v >= N_VEC) return;

    long long idx = v << 2;                         // scalar element index
    int j = (int)(idx & ((1 << L_LOG2) - 1));       // 0..2047, consecutive 4
    int i = (int)((idx >> L_LOG2) & ((1 << L_LOG2) - 1));
    int h = (int)((idx >> (2 * L_LOG2)) & NH_MASK);

    float slope = exp2f(-0.5f * (float)(h + 1));

    float4 m = mask[v];
    float base = (float)(i - j);                    // rel for j; j+1 => base-1 ...
    float4 r;
    r.x = m.x - fabsf(slope * (base - 0.0f));
    r.y = m.y - fabsf(slope * (base - 1.0f));
    r.z = m.z - fabsf(slope * (base - 2.0f));
    r.w = m.w - fabsf(slope * (base - 3.0f));
    out[v] = r;
}

extern "C" void kernel_launch(void* const* d_in, const int* in_sizes, int n_in,
                              void* d_out, int out_size) {
    // inputs: mask (B,NH,L,L) f32, q, k, v  — only mask is needed
    const float4* mask = (const float4*)d_in[0];
    float4* out = (float4*)d_out;

    const int threads = 256;
    const long long blocks = (N_VEC + threads - 1) / threads;   // 131072
    alibi_kernel<<<(unsigned)blocks, threads>>>(mask, out);
}

// round 3
// speedup vs baseline: 1.0262x; 1.0258x over previous
#include <cuda_runtime.h>
#include <cstdint>

// out[b,h,i,j] = mask[b,h,i,j] - |slope[h] * (i - j)|
// B=2, NH=16, L=2048 -> 134,217,728 fp32 = 33,554,432 float4
// slope[h] = 2^(-0.5*(h+1)) for NH=16

static constexpr int L_LOG2 = 11;            // L = 2048
static constexpr int NH_MASK = 15;           // NH = 16
static constexpr long long N_ELEM = 2LL * 16 * 2048 * 2048;
static constexpr long long N_VEC  = N_ELEM / 4;     // 33,554,432
static constexpr int THREADS = 256;
static constexpr int VPT = 4;                // float4 per thread (64 B)
// N_VEC / (THREADS*VPT) = 33,554,432 / 1024 = 32768 exactly -> no tail

__global__ __launch_bounds__(THREADS)
void alibi_kernel(const float4* __restrict__ mask, float4* __restrict__ out) {
    long long v0 = (long long)blockIdx.x * (THREADS * VPT) + threadIdx.x;

    // front-batched independent loads (MLP_p1 = 4), stride keeps 128B coalescing
    float4 m[VPT];
#pragma unroll
    for (int k = 0; k < VPT; k++)
        m[k] = __ldcs(&mask[v0 + (long long)k * THREADS]);

#pragma unroll
    for (int k = 0; k < VPT; k++) {
        long long v = v0 + (long long)k * THREADS;
        long long idx = v << 2;                          // scalar element index
        int j = (int)(idx & ((1 << L_LOG2) - 1));
        int i = (int)((idx >> L_LOG2) & ((1 << L_LOG2) - 1));
        int h = (int)((idx >> (2 * L_LOG2)) & NH_MASK);

        float slope = exp2f(-0.5f * (float)(h + 1));
        float base  = (float)(i - j);

        float4 r;
        r.x = m[k].x - fabsf(slope * (base - 0.0f));
        r.y = m[k].y - fabsf(slope * (base - 1.0f));
        r.z = m[k].z - fabsf(slope * (base - 2.0f));
        r.w = m[k].w - fabsf(slope * (base - 3.0f));
        __stcs(&out[v], r);
    }
}

extern "C" void kernel_launch(void* const* d_in, const int* in_sizes, int n_in,
                              void* d_out, int out_size) {
    const float4* mask = (const float4*)d_in[0];
    float4* out = (float4*)d_out;

    const long long blocks = N_VEC / (THREADS * VPT);   // 32768
    alibi_kernel<<<(unsigned)blocks, THREADS>>>(mask, out);
}